// round 1
// baseline (speedup 1.0000x reference)
#include <cuda_runtime.h>

#define H 512
#define W 512
#define NPTS 12
#define NMAPS 16   // B(8) * 2 groups

// One block = one (map, row). 128 threads, each thread produces 4 consecutive
// columns as a float4 store (row = 2048 B, fully coalesced).
__global__ __launch_bounds__(128) void distmaps_kernel(
    const float* __restrict__ coords,   // (8, 24, 3)
    float* __restrict__ out)            // (8, 2, 512, 512)
{
    const int row = blockIdx.x;     // 0..511
    const int map = blockIdx.y;     // 0..15 ; map = b*2 + g
    const int tid = threadIdx.x;    // 0..127

    // Stage this map's 12 points into shared memory once per block.
    __shared__ float s_y[NPTS];      // row coordinate
    __shared__ float s_xs[NPTS];     // col coordinate * 0.2f (pre-scaled)
    __shared__ float s_base[NPTS];   // 0 if valid, 1e6 if invalid

    if (tid < NPTS) {
        // point j of group g in batch b: coords[b, g*12 + j, :]
        // map = b*2+g  ->  flat point index = map*12 + j  (since 24 pts/batch)
        const float* p = coords + (map * NPTS + tid) * 3;
        float y = p[0];
        float x = p[1];
        bool invalid = fmaxf(y, x) < 0.0f;
        s_y[tid]    = y;
        s_xs[tid]   = x * 0.2f;
        s_base[tid] = invalid ? 1000000.0f : 0.0f;
    }
    __syncthreads();

    const float r = (float)row;

    // Hoist the row term: dry2[j] = base[j] + ((r - y_j)*0.2)^2
    float dry2[NPTS];
#pragma unroll
    for (int j = 0; j < NPTS; j++) {
        float t = (r - s_y[j]) * 0.2f;
        dry2[j] = fmaf(t, t, s_base[j]);
    }

    const int c0 = tid * 4;
    float res[4];
#pragma unroll
    for (int k = 0; k < 4; k++) {
        const float cs = (float)(c0 + k) * 0.2f;
        float d = 3.0e38f;
#pragma unroll
        for (int j = 0; j < NPTS; j++) {
            float dc = cs - s_xs[j];
            d = fminf(d, fmaf(dc, dc, dry2[j]));
        }
        res[k] = tanhf(2.0f * sqrtf(d));
    }

    float4 v = make_float4(res[0], res[1], res[2], res[3]);
    float4* orow = (float4*)(out + ((size_t)map * H + row) * W);
    orow[tid] = v;
}

extern "C" void kernel_launch(void* const* d_in, const int* in_sizes, int n_in,
                              void* d_out, int out_size)
{
    // coords = the input with 8*24*3 = 576 elements (x is unused).
    const float* coords = nullptr;
    for (int i = 0; i < n_in; i++) {
        if (in_sizes[i] == 8 * 24 * 3) { coords = (const float*)d_in[i]; break; }
    }
    if (!coords) coords = (const float*)d_in[n_in - 1];

    float* out = (float*)d_out;

    dim3 grid(H, NMAPS);
    dim3 block(128);
    distmaps_kernel<<<grid, block>>>(coords, out);
}

// round 2
// speedup vs baseline: 1.2163x; 1.2163x over previous
#include <cuda_runtime.h>

#define H 512
#define W 512
#define NPTS 12
#define NMAPS 16   // B(8) * 2 groups

// ---- Blackwell packed-fp32 helpers (sm_100a: only reachable via PTX) ----
__device__ __forceinline__ unsigned long long f32x2_add(unsigned long long a, unsigned long long b) {
    unsigned long long r;
    asm("add.rn.f32x2 %0, %1, %2;" : "=l"(r) : "l"(a), "l"(b));
    return r;
}
__device__ __forceinline__ unsigned long long f32x2_fma(unsigned long long a, unsigned long long b, unsigned long long c) {
    unsigned long long r;
    asm("fma.rn.f32x2 %0, %1, %2, %3;" : "=l"(r) : "l"(a), "l"(b), "l"(c));
    return r;
}
__device__ __forceinline__ unsigned long long pack2(float lo, float hi) {
    unsigned long long r;
    asm("mov.b64 %0, {%1, %2};" : "=l"(r) : "f"(lo), "f"(hi));
    return r;
}
__device__ __forceinline__ void unpack2(unsigned long long v, float& lo, float& hi) {
    asm("mov.b64 {%0, %1}, %2;" : "=f"(lo), "=f"(hi) : "l"(v));
}

// tanh(2*sqrt(d)) = 1 - 2/(exp(4*sqrt(d)) + 1), computed with MUFU approx ops.
// All-positive argument -> no cancellation; chain rel err ~1e-6.
__device__ __forceinline__ float fast_out(float d) {
    float s, t, r;
    asm("sqrt.approx.f32 %0, %1;" : "=f"(s) : "f"(d));
    float e = 5.770780163555852f * s;          // 4 * log2(e) * sqrt(d)
    asm("ex2.approx.f32 %0, %1;" : "=f"(t) : "f"(e));
    float tp1 = t + 1.0f;
    asm("rcp.approx.f32 %0, %1;" : "=f"(r) : "f"(tp1));
    return fmaf(-2.0f, r, 1.0f);               // exp overflow -> inf -> rcp 0 -> 1.0
}

// One block = (map, 2 rows). 128 threads: threads 0..63 -> row r, 64..127 -> row r+1.
// Each thread produces 8 consecutive columns (two float4 stores).
__global__ __launch_bounds__(128) void distmaps_kernel(
    const float* __restrict__ coords,   // (8, 24, 3)
    float* __restrict__ out)            // (8, 2, 512, 512)
{
    const int map = blockIdx.y;                 // 0..15
    const int tid = threadIdx.x;
    const int row = blockIdx.x * 2 + (tid >> 6);
    const int c0  = (tid & 63) * 8;

    __shared__ float s_y[NPTS];
    __shared__ float s_xs[NPTS];     // col coord * 0.2 (pre-scaled)
    __shared__ float s_base[NPTS];   // 0 valid, 1e6 invalid

    if (tid < NPTS) {
        const float* p = coords + (map * NPTS + tid) * 3;
        float y = p[0];
        float x = p[1];
        bool invalid = fmaxf(y, x) < 0.0f;
        s_y[tid]    = y;
        s_xs[tid]   = x * 0.2f;
        s_base[tid] = invalid ? 1000000.0f : 0.0f;
    }
    __syncthreads();

    const float r = (float)row;

    // Prologue: per-point packed constants.
    //   negxs2[j] = {-xs_j, -xs_j}
    //   a2[j]     = {dry2_j, dry2_j},  dry2_j = base_j + ((r - y_j)*0.2)^2
    unsigned long long negxs2[NPTS];
    unsigned long long a2[NPTS];
#pragma unroll
    for (int j = 0; j < NPTS; j++) {
        float t = (r - s_y[j]) * 0.2f;
        float a = fmaf(t, t, s_base[j]);
        float nx = -s_xs[j];
        negxs2[j] = pack2(nx, nx);
        a2[j]     = pack2(a, a);
    }

    // Mainloop: 4 column-pairs, packed fp32.
    unsigned long long csv  = pack2((float)c0 * 0.2f, (float)(c0 + 1) * 0.2f);
    const unsigned long long step = pack2(0.4f, 0.4f);

    float res[8];
#pragma unroll
    for (int p = 0; p < 4; p++) {
        float m0 = 3.0e38f, m1 = 3.0e38f;
#pragma unroll
        for (int j = 0; j < NPTS; j++) {
            unsigned long long dcv = f32x2_add(csv, negxs2[j]);       // {cs-xs, cs'-xs}
            unsigned long long dv  = f32x2_fma(dcv, dcv, a2[j]);      // {d0, d1}
            float d0, d1;
            unpack2(dv, d0, d1);
            m0 = fminf(m0, d0);                                       // alu pipe
            m1 = fminf(m1, d1);
        }
        res[2 * p]     = fast_out(m0);
        res[2 * p + 1] = fast_out(m1);
        csv = f32x2_add(csv, step);
    }

    float* orow = out + ((size_t)map * H + row) * W + c0;
    ((float4*)orow)[0] = make_float4(res[0], res[1], res[2], res[3]);
    ((float4*)orow)[1] = make_float4(res[4], res[5], res[6], res[7]);
}

extern "C" void kernel_launch(void* const* d_in, const int* in_sizes, int n_in,
                              void* d_out, int out_size)
{
    const float* coords = nullptr;
    for (int i = 0; i < n_in; i++) {
        if (in_sizes[i] == 8 * 24 * 3) { coords = (const float*)d_in[i]; break; }
    }
    if (!coords) coords = (const float*)d_in[n_in - 1];

    float* out = (float*)d_out;

    dim3 grid(H / 2, NMAPS);
    dim3 block(128);
    distmaps_kernel<<<grid, block>>>(coords, out);
}

// round 4
// speedup vs baseline: 1.4311x; 1.1766x over previous
#include <cuda_runtime.h>

#define H 512
#define W 512
#define NPTS 12
#define NMAPS 16          // B(8) * 2 groups
#define TSAT 21.0f        // d >= TSAT  ->  tanh(2*sqrt(d)) == 1.0f exactly in fp32
#define COLWIN 23.0f      // 5*sqrt(TSAT) ~ 22.9 px column influence radius

// ---- Blackwell packed-fp32 helpers ----
__device__ __forceinline__ unsigned long long f32x2_add(unsigned long long a, unsigned long long b) {
    unsigned long long r;
    asm("add.rn.f32x2 %0, %1, %2;" : "=l"(r) : "l"(a), "l"(b));
    return r;
}
__device__ __forceinline__ unsigned long long f32x2_fma(unsigned long long a, unsigned long long b, unsigned long long c) {
    unsigned long long r;
    asm("fma.rn.f32x2 %0, %1, %2, %3;" : "=l"(r) : "l"(a), "l"(b), "l"(c));
    return r;
}
__device__ __forceinline__ unsigned long long pack2(float lo, float hi) {
    unsigned long long r;
    asm("mov.b64 %0, {%1, %2};" : "=l"(r) : "f"(lo), "f"(hi));
    return r;
}
__device__ __forceinline__ void unpack2(unsigned long long v, float& lo, float& hi) {
    asm("mov.b64 {%0, %1}, %2;" : "=f"(lo), "=f"(hi) : "l"(v));
}

// tanh(2*sqrt(d)) = 1 - 2/(exp(4*sqrt(d)) + 1).  Only called for d < TSAT.
__device__ __forceinline__ float fast_out(float d) {
    float s, t, r;
    asm("sqrt.approx.f32 %0, %1;" : "=f"(s) : "f"(d));
    float e = 5.770780163555852f * s;          // 4*log2(e)*sqrt(d)
    asm("ex2.approx.f32 %0, %1;" : "=f"(t) : "f"(e));
    float tp1 = t + 1.0f;
    asm("rcp.approx.f32 %0, %1;" : "=f"(r) : "f"(tp1));
    return fmaf(-2.0f, r, 1.0f);
}

// Block = (map, 2 rows), 128 threads = 4 warps.
// warp 0: row r cols [0,256);   warp 1: row r cols [256,512)
// warp 2: row r+1 cols [0,256); warp 3: row r+1 cols [256,512)
// Each thread: 8 consecutive columns (two float4 stores).
__global__ __launch_bounds__(128) void distmaps_kernel(
    const float* __restrict__ coords,   // (8, 24, 3)
    float* __restrict__ out)            // (8, 2, 512, 512)
{
    const int map  = blockIdx.y;
    const int tid  = threadIdx.x;
    const int warp = tid >> 5;
    const int lane = tid & 31;
    const int row  = blockIdx.x * 2 + (warp >> 1);
    const int wc0  = (warp & 1) * 256;          // warp's column base
    const int c0   = wc0 + lane * 8;            // thread's first column

    __shared__ float s_y[NPTS];
    __shared__ float s_x[NPTS];      // raw col coordinate (for cull)
    __shared__ float s_base[NPTS];   // 0 valid, 1e6 invalid

    if (tid < NPTS) {
        const float* p = coords + (map * NPTS + tid) * 3;
        float y = p[0];
        float x = p[1];
        bool invalid = fmaxf(y, x) < 0.0f;
        s_y[tid]    = y;
        s_x[tid]    = x;
        s_base[tid] = invalid ? 1000000.0f : 0.0f;
    }
    __syncthreads();

    const float rowf = (float)row;
    const float wlo  = (float)wc0 - COLWIN;
    const float whi  = (float)(wc0 + 255) + COLWIN;

    // Thread's 4 packed column-pair positions (pre-scaled by 0.2).
    unsigned long long csv0 = pack2((float)c0 * 0.2f,       (float)(c0 + 1) * 0.2f);
    unsigned long long csv1 = pack2((float)(c0 + 2) * 0.2f, (float)(c0 + 3) * 0.2f);
    unsigned long long csv2 = pack2((float)(c0 + 4) * 0.2f, (float)(c0 + 5) * 0.2f);
    unsigned long long csv3 = pack2((float)(c0 + 6) * 0.2f, (float)(c0 + 7) * 0.2f);

    unsigned long long m01 = pack2(1.0e6f, 1.0e6f);
    unsigned long long m23 = m01, m45 = m01, m67 = m01;
    bool any = false;

    // Point loop with warp-uniform culling (row distance + column window).
#pragma unroll
    for (int j = 0; j < NPTS; j++) {
        float y = s_y[j];
        float x = s_x[j];
        float t = (rowf - y) * 0.2f;
        float a = fmaf(t, t, s_base[j]);
        if (a < TSAT && x > wlo && x < whi) {   // warp-uniform branch
            any = true;
            float nx = -x * 0.2f;
            unsigned long long nxv = pack2(nx, nx);
            unsigned long long av  = pack2(a, a);

            unsigned long long dc, d;
            float d0, d1, e0, e1;
            dc = f32x2_add(csv0, nxv); d = f32x2_fma(dc, dc, av);
            unpack2(m01, e0, e1); unpack2(d, d0, d1);
            m01 = pack2(fminf(e0, d0), fminf(e1, d1));
            dc = f32x2_add(csv1, nxv); d = f32x2_fma(dc, dc, av);
            unpack2(m23, e0, e1); unpack2(d, d0, d1);
            m23 = pack2(fminf(e0, d0), fminf(e1, d1));
            dc = f32x2_add(csv2, nxv); d = f32x2_fma(dc, dc, av);
            unpack2(m45, e0, e1); unpack2(d, d0, d1);
            m45 = pack2(fminf(e0, d0), fminf(e1, d1));
            dc = f32x2_add(csv3, nxv); d = f32x2_fma(dc, dc, av);
            unpack2(m67, e0, e1); unpack2(d, d0, d1);
            m67 = pack2(fminf(e0, d0), fminf(e1, d1));
        }
    }

    float* orow = out + ((size_t)map * H + row) * W + c0;
    float4 v0 = make_float4(1.0f, 1.0f, 1.0f, 1.0f);
    float4 v1 = v0;

    if (any) {
        float m[8];
        unpack2(m01, m[0], m[1]);
        unpack2(m23, m[2], m[3]);
        unpack2(m45, m[4], m[5]);
        unpack2(m67, m[6], m[7]);
        float mall = fminf(fminf(fminf(m[0], m[1]), fminf(m[2], m[3])),
                           fminf(fminf(m[4], m[5]), fminf(m[6], m[7])));
        if (mall < TSAT) {                      // per-thread: only patch threads pay MUFU
            v0.x = (m[0] < TSAT) ? fast_out(m[0]) : 1.0f;
            v0.y = (m[1] < TSAT) ? fast_out(m[1]) : 1.0f;
            v0.z = (m[2] < TSAT) ? fast_out(m[2]) : 1.0f;
            v0.w = (m[3] < TSAT) ? fast_out(m[3]) : 1.0f;
            v1.x = (m[4] < TSAT) ? fast_out(m[4]) : 1.0f;
            v1.y = (m[5] < TSAT) ? fast_out(m[5]) : 1.0f;
            v1.z = (m[6] < TSAT) ? fast_out(m[6]) : 1.0f;
            v1.w = (m[7] < TSAT) ? fast_out(m[7]) : 1.0f;
        }
    }

    ((float4*)orow)[0] = v0;
    ((float4*)orow)[1] = v1;
}

extern "C" void kernel_launch(void* const* d_in, const int* in_sizes, int n_in,
                              void* d_out, int out_size)
{
    const float* coords = nullptr;
    for (int i = 0; i < n_in; i++) {
        if (in_sizes[i] == 8 * 24 * 3) { coords = (const float*)d_in[i]; break; }
    }
    if (!coords) coords = (const float*)d_in[n_in - 1];

    float* out = (float*)d_out;

    dim3 grid(H / 2, NMAPS);
    dim3 block(128);
    distmaps_kernel<<<grid, block>>>(coords, out);
}

// round 5
// speedup vs baseline: 1.4485x; 1.0121x over previous
#include <cuda_runtime.h>

#define H 512
#define W 512
#define NPTS 12
#define NMAPS 16          // B(8) * 2 groups
#define TSAT 21.0f        // d >= TSAT -> tanh(2*sqrt(d)) == 1.0f exactly in fp32
#define PRAD 23           // patch radius in pixels (5*sqrt(21) ~ 22.91)
#define PROWS 47          // 2*PRAD + 1
#define PCOL4 13          // ceil((2*PRAD+1 + 3alignment)/4) float4 columns
#define PUNITS (PROWS * PCOL4)   // 611

// ---- packed fp32 helpers ----
__device__ __forceinline__ unsigned long long f32x2_add(unsigned long long a, unsigned long long b) {
    unsigned long long r;
    asm("add.rn.f32x2 %0, %1, %2;" : "=l"(r) : "l"(a), "l"(b));
    return r;
}
__device__ __forceinline__ unsigned long long f32x2_fma(unsigned long long a, unsigned long long b, unsigned long long c) {
    unsigned long long r;
    asm("fma.rn.f32x2 %0, %1, %2, %3;" : "=l"(r) : "l"(a), "l"(b), "l"(c));
    return r;
}
__device__ __forceinline__ unsigned long long pack2(float lo, float hi) {
    unsigned long long r;
    asm("mov.b64 %0, {%1, %2};" : "=l"(r) : "f"(lo), "f"(hi));
    return r;
}
__device__ __forceinline__ void unpack2(unsigned long long v, float& lo, float& hi) {
    asm("mov.b64 {%0, %1}, %2;" : "=f"(lo), "=f"(hi) : "l"(v));
}

// tanh(2*sqrt(d)) = 1 - 2/(exp(4*sqrt(d)) + 1); only called with d < TSAT.
__device__ __forceinline__ float fast_out(float d) {
    float s, t, r;
    asm("sqrt.approx.f32 %0, %1;" : "=f"(s) : "f"(d));
    float e = 5.770780163555852f * s;          // 4*log2(e)*sqrt(d)
    asm("ex2.approx.f32 %0, %1;" : "=f"(t) : "f"(e));
    float tp1 = t + 1.0f;
    asm("rcp.approx.f32 %0, %1;" : "=f"(r) : "f"(tp1));
    return fmaf(-2.0f, r, 1.0f);
}

// ---- Kernel 1: fill everything with 1.0f (pure stores) ----
// 2048 blocks x 256 threads, 2 float4 per thread = 1,048,576 float4 total.
__global__ __launch_bounds__(256) void fill_kernel(float4* __restrict__ out)
{
    const float4 one = make_float4(1.0f, 1.0f, 1.0f, 1.0f);
    unsigned idx = blockIdx.x * 512u + threadIdx.x;
    out[idx]       = one;
    out[idx + 256] = one;
}

// ---- Kernel 2: one block per (map, point); overwrite the 47x52 bbox ----
// Each pixel gets the FULL 12-point min => overlapping patches write identical
// values (benign duplicates), and fill->patch stream order makes it exact.
__global__ __launch_bounds__(256) void patch_kernel(
    const float* __restrict__ coords,   // (8, 24, 3)
    float* __restrict__ out)            // (8, 2, 512, 512)
{
    const int m = blockIdx.x / NPTS;    // map 0..15
    const int p = blockIdx.x % NPTS;    // point 0..11
    const int tid = threadIdx.x;

    __shared__ float s_y[NPTS];      // raw row coord
    __shared__ float s_x[NPTS];      // raw col coord
    __shared__ float s_nx[NPTS];     // -x * 0.2
    __shared__ float s_base[NPTS];   // 0 valid, 1e6 invalid

    if (tid < NPTS) {
        const float* q = coords + (m * NPTS + tid) * 3;
        float y = q[0];
        float x = q[1];
        bool invalid = fmaxf(y, x) < 0.0f;
        s_y[tid]    = y;
        s_x[tid]    = x;
        s_nx[tid]   = -x * 0.2f;
        s_base[tid] = invalid ? 1000000.0f : 0.0f;
    }
    __syncthreads();

    if (s_base[p] != 0.0f) return;      // invalid anchor point: no patch

    const int iy = (int)floorf(s_y[p]);
    const int ix = (int)floorf(s_x[p]);
    const int r0 = iy - PRAD;
    const int cb = (ix - PRAD) & ~3;    // float4-aligned (rounds toward -inf)

    for (int u = tid; u < PUNITS; u += 256) {
        const int r = r0 + u / PCOL4;
        const int c = cb + (u % PCOL4) * 4;
        if (r < 0 || r >= H || c < 0 || c > W - 4) continue;

        const float rf = (float)r;
        unsigned long long cs0 = pack2((float)c * 0.2f,       (float)(c + 1) * 0.2f);
        unsigned long long cs1 = pack2((float)(c + 2) * 0.2f, (float)(c + 3) * 0.2f);

        float m0 = 1.0e6f, m1 = 1.0e6f, m2 = 1.0e6f, m3 = 1.0e6f;
#pragma unroll
        for (int j = 0; j < NPTS; j++) {
            float t = (rf - s_y[j]) * 0.2f;
            float a = fmaf(t, t, s_base[j]);
            unsigned long long nxv = pack2(s_nx[j], s_nx[j]);
            unsigned long long av  = pack2(a, a);
            unsigned long long dc, d;
            float d0, d1;
            dc = f32x2_add(cs0, nxv); d = f32x2_fma(dc, dc, av);
            unpack2(d, d0, d1); m0 = fminf(m0, d0); m1 = fminf(m1, d1);
            dc = f32x2_add(cs1, nxv); d = f32x2_fma(dc, dc, av);
            unpack2(d, d0, d1); m2 = fminf(m2, d0); m3 = fminf(m3, d1);
        }

        float4 v;
        v.x = (m0 < TSAT) ? fast_out(m0) : 1.0f;
        v.y = (m1 < TSAT) ? fast_out(m1) : 1.0f;
        v.z = (m2 < TSAT) ? fast_out(m2) : 1.0f;
        v.w = (m3 < TSAT) ? fast_out(m3) : 1.0f;

        *(float4*)(out + ((size_t)m * H + r) * W + c) = v;
    }
}

extern "C" void kernel_launch(void* const* d_in, const int* in_sizes, int n_in,
                              void* d_out, int out_size)
{
    const float* coords = nullptr;
    for (int i = 0; i < n_in; i++) {
        if (in_sizes[i] == 8 * 24 * 3) { coords = (const float*)d_in[i]; break; }
    }
    if (!coords) coords = (const float*)d_in[n_in - 1];

    float* out = (float*)d_out;

    fill_kernel<<<2048, 256>>>((float4*)out);          // 1.0f everywhere
    patch_kernel<<<NMAPS * NPTS, 256>>>(coords, out);  // overwrite bboxes
}